// round 2
// baseline (speedup 1.0000x reference)
#include <cuda_runtime.h>
#include <math.h>
#include <stdint.h>

#define N_NODES 4096
#define F 256
#define H 4
#define HD 64
#define WPR (N_NODES / 32)   // 128 bitmap words per row
#define MAXN 512             // max neighbors per row (avg 33, Poisson tail safe)

// ---- scratch (static device arrays; no allocations allowed) ----
__device__ float g_Q[N_NODES * F];
__device__ float g_K[N_NODES * F];
__device__ float g_V[N_NODES * F];
__device__ unsigned g_adj[N_NODES * WPR];

// packed fp32x2 FMA (Blackwell sm_100a+)
__device__ __forceinline__ void ffma2(float2& c, const float2& a, const float2& b) {
    unsigned long long A = *(const unsigned long long*)&a;
    unsigned long long B = *(const unsigned long long*)&b;
    unsigned long long C = *(unsigned long long*)&c;
    asm("fma.rn.f32x2 %0, %1, %2, %3;" : "=l"(C) : "l"(A), "l"(B), "l"(C));
    *(unsigned long long*)&c = C;
}

// ---------------------------------------------------------------------------
// Adjacency bitmap build
// ---------------------------------------------------------------------------
__global__ void zero_adj_kernel() {
    int i = blockIdx.x * blockDim.x + threadIdx.x;
    if (i < N_NODES * WPR) g_adj[i] = 0u;
}

__global__ void scatter_edges_kernel(const int* __restrict__ ei, int E) {
    int i = blockIdx.x * blockDim.x + threadIdx.x;
    if (i >= E) return;
    int s = ei[i];
    int d = ei[E + i];
    atomicOr(&g_adj[s * WPR + (d >> 5)], 1u << (d & 31));
}

// ---------------------------------------------------------------------------
// Fused QKV projection: y = x @ W^T + b for Wq, Wk, Wv
// BM=128, BN=64, BK=16, 256 threads, 8x4 per thread, packed f32x2 FMA.
// blockIdx.y in [0,12): 4 column-blocks per matrix.
// A tile transposed in smem; B tile transposed AND each value duplicated so
// broadcast pairs (b,b) are loaded directly with LDS.128 (no mov.b64 packing).
// ---------------------------------------------------------------------------
#define BM 128
#define BN 64
#define BK 16

__global__ __launch_bounds__(256, 4)
void qkv_gemm_kernel(const float* __restrict__ x,
                     const float* __restrict__ Wq, const float* __restrict__ bq,
                     const float* __restrict__ Wk, const float* __restrict__ bk,
                     const float* __restrict__ Wv, const float* __restrict__ bv) {
    __shared__ float Ast[BK][BM + 4];        // transposed A tile
    __shared__ float Bst2[BK][2 * BN + 4];   // transposed + duplicated W tile

    const int tid = threadIdx.x;        // 256
    const int tx = tid & 15;            // output col group (4 cols)
    const int ty = tid >> 4;            // output row group (8 rows)
    const int r0 = blockIdx.x * BM;
    const int by = blockIdx.y;          // 0..11
    const int mat = by >> 2;

    const float* W    = (mat == 0) ? Wq : (mat == 1) ? Wk : Wv;
    const float* bias = (mat == 0) ? bq : (mat == 1) ? bk : bv;
    float*       out  = (mat == 0) ? g_Q : (mat == 1) ? g_K : g_V;
    const int o0 = (by & 3) * BN;

    // acc2[rp][j]: row-pair (2rp, 2rp+1) x col j
    float2 acc2[4][4];
#pragma unroll
    for (int i = 0; i < 4; i++)
#pragma unroll
        for (int j = 0; j < 4; j++) acc2[i][j] = make_float2(0.f, 0.f);

    for (int k0 = 0; k0 < F; k0 += BK) {
        // A tile (128x16) transposed: 2 float4 per thread
#pragma unroll
        for (int it = 0; it < 2; it++) {
            int lin = tid + it * 256;
            int r = lin >> 2;
            int kc = lin & 3;
            float4 v = *(const float4*)&x[(r0 + r) * F + k0 + kc * 4];
            Ast[kc * 4 + 0][r] = v.x;
            Ast[kc * 4 + 1][r] = v.y;
            Ast[kc * 4 + 2][r] = v.z;
            Ast[kc * 4 + 3][r] = v.w;
        }
        // B tile (64 outs x 16 k) transposed + duplicated: 1 float4 per thread
        {
            int o = tid >> 2;
            int kc = tid & 3;
            float4 v = *(const float4*)&W[(o0 + o) * F + k0 + kc * 4];
            Bst2[kc * 4 + 0][2 * o] = v.x; Bst2[kc * 4 + 0][2 * o + 1] = v.x;
            Bst2[kc * 4 + 1][2 * o] = v.y; Bst2[kc * 4 + 1][2 * o + 1] = v.y;
            Bst2[kc * 4 + 2][2 * o] = v.z; Bst2[kc * 4 + 2][2 * o + 1] = v.z;
            Bst2[kc * 4 + 3][2 * o] = v.w; Bst2[kc * 4 + 3][2 * o + 1] = v.w;
        }
        __syncthreads();

#pragma unroll
        for (int kk = 0; kk < BK; kk++) {
            float4 a0 = *(const float4*)&Ast[kk][ty * 8];
            float4 a1 = *(const float4*)&Ast[kk][ty * 8 + 4];
            float4 b01 = *(const float4*)&Bst2[kk][tx * 8];      // (b0,b0,b1,b1)
            float4 b23 = *(const float4*)&Bst2[kk][tx * 8 + 4];  // (b2,b2,b3,b3)
            float2 ap[4] = { make_float2(a0.x, a0.y), make_float2(a0.z, a0.w),
                             make_float2(a1.x, a1.y), make_float2(a1.z, a1.w) };
            float2 bp[4] = { make_float2(b01.x, b01.y), make_float2(b01.z, b01.w),
                             make_float2(b23.x, b23.y), make_float2(b23.z, b23.w) };
#pragma unroll
            for (int i = 0; i < 4; i++)
#pragma unroll
                for (int j = 0; j < 4; j++) ffma2(acc2[i][j], ap[i], bp[j]);
        }
        __syncthreads();
    }

#pragma unroll
    for (int i = 0; i < 4; i++) {
        int r = r0 + ty * 8 + i * 2;
#pragma unroll
        for (int j = 0; j < 4; j++) {
            int o = o0 + tx * 4 + j;
            float bo = bias[o];
            out[(r + 0) * F + o] = acc2[i][j].x + bo;
            out[(r + 1) * F + o] = acc2[i][j].y + bo;
        }
    }
}

// ---------------------------------------------------------------------------
// Fused sparse attention + attn-matrix materialization + residual + LayerNorm
// One block (128 threads = 4 warps) per node row. Warp w owns head w.
// ---------------------------------------------------------------------------
__global__ __launch_bounds__(128, 8)
void attn_kernel(const float* __restrict__ x,
                 const float* __restrict__ ln_g, const float* __restrict__ ln_b,
                 float* __restrict__ out, float* __restrict__ attn) {
    const int row  = blockIdx.x;
    const int tid  = threadIdx.x;
    const int w    = tid >> 5;   // head
    const int lane = tid & 31;

    // (1) Stream zeros over this block's 4 attn rows. Fire-and-forget stores;
    // ordered before the probability scatter by the __syncthreads fences below.
    {
        float4 z = make_float4(0.f, 0.f, 0.f, 0.f);
        float4* dst = (float4*)(attn + (size_t)w * N_NODES * N_NODES +
                                (size_t)row * N_NODES);
#pragma unroll
        for (int i = 0; i < (N_NODES / 4) / 32; i++)   // 32 float4 per lane
            dst[i * 32 + lane] = z;
    }

    __shared__ int   s_nbr[MAXN];
    __shared__ float s_scores[H][MAXN];
    __shared__ float s_q[F];
    __shared__ float s_y[F];
    __shared__ int   s_warpcnt[4];
    __shared__ int   s_cnt;
    __shared__ float s_red[8];

    // Q row into smem
    s_q[tid]       = g_Q[row * F + tid];
    s_q[tid + 128] = g_Q[row * F + tid + 128];

    // (2) Extract neighbor list from bitmap, deterministic (scan-based, sorted)
    unsigned word = g_adj[row * WPR + tid];
    int c = __popc(word);
    int sc = c;  // warp inclusive scan
#pragma unroll
    for (int d = 1; d < 32; d <<= 1) {
        int v = __shfl_up_sync(0xffffffffu, sc, d);
        if (lane >= d) sc += v;
    }
    if (lane == 31) s_warpcnt[w] = sc;
    __syncthreads();

    int base = 0;
#pragma unroll
    for (int i = 0; i < 4; i++)
        if (i < w) base += s_warpcnt[i];
    int off = base + sc - c;   // exclusive prefix across the block
    unsigned ww = word;
    while (ww) {
        int b = __ffs(ww) - 1;
        ww &= ww - 1;
        if (off < MAXN) s_nbr[off] = (tid << 5) + b;
        off++;
    }
    if (tid == 127) s_cnt = base + sc;
    __syncthreads();

    int cnt = s_cnt;
    if (cnt > MAXN) cnt = MAXN;

    // (3) Scores: warp w computes Q_h . K_h for each neighbor
    const float invsqrt = 0.125f;  // 1/sqrt(64)
    float2 qh;
    qh.x = s_q[w * HD + lane * 2];
    qh.y = s_q[w * HD + lane * 2 + 1];
    for (int j = 0; j < cnt; j++) {
        int m = s_nbr[j];
        float2 kv = *(const float2*)&g_K[m * F + w * HD + lane * 2];
        float p = qh.x * kv.x + qh.y * kv.y;
#pragma unroll
        for (int d = 16; d; d >>= 1) p += __shfl_xor_sync(0xffffffffu, p, d);
        if (lane == 0) s_scores[w][j] = p * invsqrt;
    }
    __syncwarp();

    // (4) Softmax over neighbors (per warp/head)
    float mx = -INFINITY;
    for (int j = lane; j < cnt; j += 32) mx = fmaxf(mx, s_scores[w][j]);
#pragma unroll
    for (int d = 16; d; d >>= 1) mx = fmaxf(mx, __shfl_xor_sync(0xffffffffu, mx, d));
    float sum = 0.0f;
    for (int j = lane; j < cnt; j += 32) {
        float e = expf(s_scores[w][j] - mx);
        s_scores[w][j] = e;
        sum += e;
    }
#pragma unroll
    for (int d = 16; d; d >>= 1) sum += __shfl_xor_sync(0xffffffffu, sum, d);
    float inv = 1.0f / sum;

    // (5) Normalize + scatter nonzero probabilities into the zeroed attn rows.
    // Zero-stores above are ordered before these by the intervening
    // __syncthreads (block-level memory fence + barrier).
    for (int j = lane; j < cnt; j += 32) {
        float p = s_scores[w][j] * inv;
        s_scores[w][j] = p;
        attn[(size_t)w * N_NODES * N_NODES + (size_t)row * N_NODES + s_nbr[j]] = p;
    }
    __syncwarp();

    // (6) out_h = sum_j p_j * V[nbr_j, h]
    float2 acc = make_float2(0.f, 0.f);
    for (int j = 0; j < cnt; j++) {
        float p = s_scores[w][j];
        int m = s_nbr[j];
        float2 v = *(const float2*)&g_V[m * F + w * HD + lane * 2];
        acc.x += p * v.x;
        acc.y += p * v.y;
    }
    s_y[w * HD + lane * 2]     = acc.x;
    s_y[w * HD + lane * 2 + 1] = acc.y;
    __syncthreads();

    // (7) residual + LayerNorm over 256 channels (2 per thread)
    float y0 = s_y[tid * 2]     + x[row * F + tid * 2];
    float y1 = s_y[tid * 2 + 1] + x[row * F + tid * 2 + 1];
    float ps = y0 + y1;
    float pq = y0 * y0 + y1 * y1;
#pragma unroll
    for (int d = 16; d; d >>= 1) {
        ps += __shfl_xor_sync(0xffffffffu, ps, d);
        pq += __shfl_xor_sync(0xffffffffu, pq, d);
    }
    if (lane == 0) { s_red[w] = ps; s_red[4 + w] = pq; }
    __syncthreads();
    float tot  = s_red[0] + s_red[1] + s_red[2] + s_red[3];
    float totq = s_red[4] + s_red[5] + s_red[6] + s_red[7];
    float mu  = tot * (1.0f / 256.0f);
    float var = totq * (1.0f / 256.0f) - mu * mu;
    float rs  = rsqrtf(var + 1e-5f);
    out[row * F + tid * 2]     = (y0 - mu) * rs * ln_g[tid * 2]     + ln_b[tid * 2];
    out[row * F + tid * 2 + 1] = (y1 - mu) * rs * ln_g[tid * 2 + 1] + ln_b[tid * 2 + 1];
}

// ---------------------------------------------------------------------------
extern "C" void kernel_launch(void* const* d_in, const int* in_sizes, int n_in,
                              void* d_out, int out_size) {
    const float* x  = (const float*)d_in[0];
    const int*   ei = (const int*)d_in[1];
    const float* Wq = (const float*)d_in[2];
    const float* bq = (const float*)d_in[3];
    const float* Wk = (const float*)d_in[4];
    const float* bk = (const float*)d_in[5];
    const float* Wv = (const float*)d_in[6];
    const float* bv = (const float*)d_in[7];
    const float* lg = (const float*)d_in[8];
    const float* lb = (const float*)d_in[9];

    const int E = in_sizes[1] / 2;

    float* out  = (float*)d_out;                 // [1, 4096, 256]
    float* attn = out + (size_t)N_NODES * F;     // [1, 4, 4096, 4096]

    zero_adj_kernel<<<(N_NODES * WPR + 255) / 256, 256>>>();
    scatter_edges_kernel<<<(E + 255) / 256, 256>>>(ei, E);

    dim3 gg(N_NODES / BM, 12);
    qkv_gemm_kernel<<<gg, 256>>>(x, Wq, bq, Wk, bk, Wv, bv);

    attn_kernel<<<N_NODES, 128>>>(x, lg, lb, out, attn);
}

// round 3
// speedup vs baseline: 1.2092x; 1.2092x over previous
#include <cuda_runtime.h>
#include <math.h>
#include <stdint.h>

#define N_NODES 4096
#define F 256
#define H 4
#define HD 64
#define WPR (N_NODES / 32)   // 128 bitmap words per row
#define MAXN 256             // max neighbors per row (avg 33; +12 sigma safe)

// ---- scratch (static device arrays; no allocations allowed) ----
__device__ float g_Q[N_NODES * F];
__device__ float g_K[N_NODES * F];
__device__ float g_V[N_NODES * F];
__device__ unsigned g_adj[N_NODES * WPR];

// packed fp32x2 FMA (Blackwell sm_100a+)
__device__ __forceinline__ void ffma2(float2& c, const float2& a, const float2& b) {
    unsigned long long A = *(const unsigned long long*)&a;
    unsigned long long B = *(const unsigned long long*)&b;
    unsigned long long C = *(unsigned long long*)&c;
    asm("fma.rn.f32x2 %0, %1, %2, %3;" : "=l"(C) : "l"(A), "l"(B), "l"(C));
    *(unsigned long long*)&c = C;
}

// ---------------------------------------------------------------------------
// Adjacency bitmap build
// ---------------------------------------------------------------------------
__global__ void zero_adj_kernel() {
    int i = blockIdx.x * blockDim.x + threadIdx.x;
    if (i < N_NODES * WPR) g_adj[i] = 0u;
}

__global__ void scatter_edges_kernel(const int* __restrict__ ei, int E) {
    int i = blockIdx.x * blockDim.x + threadIdx.x;
    if (i >= E) return;
    int s = ei[i];
    int d = ei[E + i];
    atomicOr(&g_adj[s * WPR + (d >> 5)], 1u << (d & 31));
}

// ---------------------------------------------------------------------------
// Fused QKV projection + attn-matrix zeroing.
// GEMM is FMA-bound with idle DRAM; each block also streams a zero slice of
// the 268MB attn tensor (fire-and-forget STG.128) interleaved with the k-loop.
// BM=128, BN=64, BK=16, 256 threads, 8x4 per thread, packed f32x2 FMA.
// ---------------------------------------------------------------------------
#define BM 128
#define BN 64
#define BK 16
#define NBLK 384                               // 32 x 12 blocks
#define TOT4 16777216u                         // H*N*N/4 float4's to zero
#define SLICE 43692u                           // ceil(TOT4 / NBLK)
#define ZPT 11                                 // zero-stores per thread per k-iter

__global__ __launch_bounds__(256, 4)
void qkv_gemm_kernel(const float* __restrict__ x,
                     const float* __restrict__ Wq, const float* __restrict__ bq,
                     const float* __restrict__ Wk, const float* __restrict__ bk,
                     const float* __restrict__ Wv, const float* __restrict__ bv,
                     float* __restrict__ attn) {
    __shared__ float Ast[BK][BM + 4];        // transposed A tile
    __shared__ float Bst2[BK][2 * BN + 4];   // transposed + duplicated W tile

    const int tid = threadIdx.x;        // 256
    const int tx = tid & 15;            // output col group (4 cols)
    const int ty = tid >> 4;            // output row group (8 rows)
    const int r0 = blockIdx.x * BM;
    const int by = blockIdx.y;          // 0..11
    const int mat = by >> 2;

    const float* W    = (mat == 0) ? Wq : (mat == 1) ? Wk : Wv;
    const float* bias = (mat == 0) ? bq : (mat == 1) ? bk : bv;
    float*       out  = (mat == 0) ? g_Q : (mat == 1) ? g_K : g_V;
    const int o0 = (by & 3) * BN;

    // zero-slice bounds for this block
    const unsigned bid = by * gridDim.x + blockIdx.x;
    const unsigned zs = bid * SLICE;
    const unsigned ze = (zs + SLICE < TOT4) ? zs + SLICE : TOT4;
    float4* __restrict__ zp = (float4*)attn;
    const float4 zero4 = make_float4(0.f, 0.f, 0.f, 0.f);

    float2 acc2[4][4];
#pragma unroll
    for (int i = 0; i < 4; i++)
#pragma unroll
        for (int j = 0; j < 4; j++) acc2[i][j] = make_float2(0.f, 0.f);

    int iter = 0;
    for (int k0 = 0; k0 < F; k0 += BK, iter++) {
        // A tile (128x16) transposed: 2 float4 per thread
#pragma unroll
        for (int it = 0; it < 2; it++) {
            int lin = tid + it * 256;
            int r = lin >> 2;
            int kc = lin & 3;
            float4 v = *(const float4*)&x[(r0 + r) * F + k0 + kc * 4];
            Ast[kc * 4 + 0][r] = v.x;
            Ast[kc * 4 + 1][r] = v.y;
            Ast[kc * 4 + 2][r] = v.z;
            Ast[kc * 4 + 3][r] = v.w;
        }
        // B tile (64 outs x 16 k) transposed + duplicated: 1 float4 per thread
        {
            int o = tid >> 2;
            int kc = tid & 3;
            float4 v = *(const float4*)&W[(o0 + o) * F + k0 + kc * 4];
            Bst2[kc * 4 + 0][2 * o] = v.x; Bst2[kc * 4 + 0][2 * o + 1] = v.x;
            Bst2[kc * 4 + 1][2 * o] = v.y; Bst2[kc * 4 + 1][2 * o + 1] = v.y;
            Bst2[kc * 4 + 2][2 * o] = v.z; Bst2[kc * 4 + 2][2 * o + 1] = v.z;
            Bst2[kc * 4 + 3][2 * o] = v.w; Bst2[kc * 4 + 3][2 * o + 1] = v.w;
        }

        // interleaved zero-streaming of the attn slice (fire-and-forget)
#pragma unroll
        for (int t = 0; t < ZPT; t++) {
            unsigned idx = zs + (unsigned)(iter * ZPT + t) * 256u + (unsigned)tid;
            if (idx < ze) zp[idx] = zero4;
        }

        __syncthreads();

#pragma unroll
        for (int kk = 0; kk < BK; kk++) {
            float4 a0 = *(const float4*)&Ast[kk][ty * 8];
            float4 a1 = *(const float4*)&Ast[kk][ty * 8 + 4];
            float4 b01 = *(const float4*)&Bst2[kk][tx * 8];      // (b0,b0,b1,b1)
            float4 b23 = *(const float4*)&Bst2[kk][tx * 8 + 4];  // (b2,b2,b3,b3)
            float2 ap[4] = { make_float2(a0.x, a0.y), make_float2(a0.z, a0.w),
                             make_float2(a1.x, a1.y), make_float2(a1.z, a1.w) };
            float2 bp[4] = { make_float2(b01.x, b01.y), make_float2(b01.z, b01.w),
                             make_float2(b23.x, b23.y), make_float2(b23.z, b23.w) };
#pragma unroll
            for (int i = 0; i < 4; i++)
#pragma unroll
                for (int j = 0; j < 4; j++) ffma2(acc2[i][j], ap[i], bp[j]);
        }
        __syncthreads();
    }

#pragma unroll
    for (int i = 0; i < 4; i++) {
        int r = r0 + ty * 8 + i * 2;
#pragma unroll
        for (int j = 0; j < 4; j++) {
            int o = o0 + tx * 4 + j;
            float bo = bias[o];
            out[(r + 0) * F + o] = acc2[i][j].x + bo;
            out[(r + 1) * F + o] = acc2[i][j].y + bo;
        }
    }
}

// ---------------------------------------------------------------------------
// Fused sparse attention (scatter into pre-zeroed attn) + residual + LayerNorm
// One block (128 threads = 4 warps) per node row. Warp w owns head w.
// ---------------------------------------------------------------------------
__global__ __launch_bounds__(128, 8)
void attn_kernel(const float* __restrict__ x,
                 const float* __restrict__ ln_g, const float* __restrict__ ln_b,
                 float* __restrict__ out, float* __restrict__ attn) {
    const int row  = blockIdx.x;
    const int tid  = threadIdx.x;
    const int w    = tid >> 5;   // head
    const int lane = tid & 31;

    __shared__ int   s_nbr[MAXN];
    __shared__ float s_scores[H][MAXN];
    __shared__ float s_q[F];
    __shared__ float s_y[F];
    __shared__ int   s_warpcnt[4];
    __shared__ int   s_cnt;
    __shared__ float s_red[8];

    // Q row into smem
    s_q[tid]       = g_Q[row * F + tid];
    s_q[tid + 128] = g_Q[row * F + tid + 128];

    // (1) Extract neighbor list from bitmap, deterministic (scan-based, sorted)
    unsigned word = g_adj[row * WPR + tid];
    int c = __popc(word);
    int sc = c;  // warp inclusive scan
#pragma unroll
    for (int d = 1; d < 32; d <<= 1) {
        int v = __shfl_up_sync(0xffffffffu, sc, d);
        if (lane >= d) sc += v;
    }
    if (lane == 31) s_warpcnt[w] = sc;
    __syncthreads();

    int base = 0;
#pragma unroll
    for (int i = 0; i < 4; i++)
        if (i < w) base += s_warpcnt[i];
    int off = base + sc - c;   // exclusive prefix across the block
    unsigned ww = word;
    while (ww) {
        int b = __ffs(ww) - 1;
        ww &= ww - 1;
        if (off < MAXN) s_nbr[off] = (tid << 5) + b;
        off++;
    }
    if (tid == 127) s_cnt = base + sc;
    __syncthreads();

    int cnt = s_cnt;
    if (cnt > MAXN) cnt = MAXN;

    // (2) Scores: warp w computes Q_h . K_h, 4 neighbors in flight (ILP across
    // independent shfl reduction trees)
    const float invsqrt = 0.125f;  // 1/sqrt(64)
    float2 qh;
    qh.x = s_q[w * HD + lane * 2];
    qh.y = s_q[w * HD + lane * 2 + 1];
    const float* __restrict__ Kbase = g_K + w * HD + lane * 2;
    int j = 0;
    for (; j + 4 <= cnt; j += 4) {
        int m0 = s_nbr[j], m1 = s_nbr[j + 1], m2 = s_nbr[j + 2], m3 = s_nbr[j + 3];
        float2 k0 = *(const float2*)(Kbase + m0 * F);
        float2 k1 = *(const float2*)(Kbase + m1 * F);
        float2 k2 = *(const float2*)(Kbase + m2 * F);
        float2 k3 = *(const float2*)(Kbase + m3 * F);
        float p0 = qh.x * k0.x + qh.y * k0.y;
        float p1 = qh.x * k1.x + qh.y * k1.y;
        float p2 = qh.x * k2.x + qh.y * k2.y;
        float p3 = qh.x * k3.x + qh.y * k3.y;
#pragma unroll
        for (int d = 16; d; d >>= 1) {
            p0 += __shfl_xor_sync(0xffffffffu, p0, d);
            p1 += __shfl_xor_sync(0xffffffffu, p1, d);
            p2 += __shfl_xor_sync(0xffffffffu, p2, d);
            p3 += __shfl_xor_sync(0xffffffffu, p3, d);
        }
        if (lane == 0) {
            s_scores[w][j]     = p0 * invsqrt;
            s_scores[w][j + 1] = p1 * invsqrt;
            s_scores[w][j + 2] = p2 * invsqrt;
            s_scores[w][j + 3] = p3 * invsqrt;
        }
    }
    for (; j < cnt; j++) {
        int m = s_nbr[j];
        float2 kv = *(const float2*)(Kbase + m * F);
        float p = qh.x * kv.x + qh.y * kv.y;
#pragma unroll
        for (int d = 16; d; d >>= 1) p += __shfl_xor_sync(0xffffffffu, p, d);
        if (lane == 0) s_scores[w][j] = p * invsqrt;
    }
    __syncwarp();

    // (3) Softmax over neighbors (per warp/head)
    float mx = -INFINITY;
    for (int t = lane; t < cnt; t += 32) mx = fmaxf(mx, s_scores[w][t]);
#pragma unroll
    for (int d = 16; d; d >>= 1) mx = fmaxf(mx, __shfl_xor_sync(0xffffffffu, mx, d));
    float sum = 0.0f;
    for (int t = lane; t < cnt; t += 32) {
        float e = expf(s_scores[w][t] - mx);
        s_scores[w][t] = e;
        sum += e;
    }
#pragma unroll
    for (int d = 16; d; d >>= 1) sum += __shfl_xor_sync(0xffffffffu, sum, d);
    float inv = 1.0f / sum;

    // (4) Normalize + scatter nonzero probabilities over the pre-zeroed attn
    // rows (zeroed by qkv_gemm_kernel; cross-kernel stream order fences it).
    for (int t = lane; t < cnt; t += 32) {
        float p = s_scores[w][t] * inv;
        s_scores[w][t] = p;
        attn[(size_t)w * N_NODES * N_NODES + (size_t)row * N_NODES + s_nbr[t]] = p;
    }
    __syncwarp();

    // (5) out_h = sum_j p_j * V[nbr_j, h] — 4 independent accumulators
    const float* __restrict__ Vbase = g_V + w * HD + lane * 2;
    float2 a0 = make_float2(0.f, 0.f), a1 = make_float2(0.f, 0.f);
    float2 a2 = make_float2(0.f, 0.f), a3 = make_float2(0.f, 0.f);
    j = 0;
    for (; j + 4 <= cnt; j += 4) {
        float p0 = s_scores[w][j],     p1 = s_scores[w][j + 1];
        float p2 = s_scores[w][j + 2], p3 = s_scores[w][j + 3];
        float2 v0 = *(const float2*)(Vbase + s_nbr[j] * F);
        float2 v1 = *(const float2*)(Vbase + s_nbr[j + 1] * F);
        float2 v2 = *(const float2*)(Vbase + s_nbr[j + 2] * F);
        float2 v3 = *(const float2*)(Vbase + s_nbr[j + 3] * F);
        a0.x += p0 * v0.x; a0.y += p0 * v0.y;
        a1.x += p1 * v1.x; a1.y += p1 * v1.y;
        a2.x += p2 * v2.x; a2.y += p2 * v2.y;
        a3.x += p3 * v3.x; a3.y += p3 * v3.y;
    }
    for (; j < cnt; j++) {
        float p = s_scores[w][j];
        float2 v = *(const float2*)(Vbase + s_nbr[j] * F);
        a0.x += p * v.x; a0.y += p * v.y;
    }
    float2 acc;
    acc.x = (a0.x + a1.x) + (a2.x + a3.x);
    acc.y = (a0.y + a1.y) + (a2.y + a3.y);
    s_y[w * HD + lane * 2]     = acc.x;
    s_y[w * HD + lane * 2 + 1] = acc.y;
    __syncthreads();

    // (6) residual + LayerNorm over 256 channels (2 per thread)
    float y0 = s_y[tid * 2]     + x[row * F + tid * 2];
    float y1 = s_y[tid * 2 + 1] + x[row * F + tid * 2 + 1];
    float ps = y0 + y1;
    float pq = y0 * y0 + y1 * y1;
#pragma unroll
    for (int d = 16; d; d >>= 1) {
        ps += __shfl_xor_sync(0xffffffffu, ps, d);
        pq += __shfl_xor_sync(0xffffffffu, pq, d);
    }
    if (lane == 0) { s_red[w] = ps; s_red[4 + w] = pq; }
    __syncthreads();
    float tot  = s_red[0] + s_red[1] + s_red[2] + s_red[3];
    float totq = s_red[4] + s_red[5] + s_red[6] + s_red[7];
    float mu  = tot * (1.0f / 256.0f);
    float var = totq * (1.0f / 256.0f) - mu * mu;
    float rs  = rsqrtf(var + 1e-5f);
    out[row * F + tid * 2]     = (y0 - mu) * rs * ln_g[tid * 2]     + ln_b[tid * 2];
    out[row * F + tid * 2 + 1] = (y1 - mu) * rs * ln_g[tid * 2 + 1] + ln_b[tid * 2 + 1];
}

// ---------------------------------------------------------------------------
extern "C" void kernel_launch(void* const* d_in, const int* in_sizes, int n_in,
                              void* d_out, int out_size) {
    const float* x  = (const float*)d_in[0];
    const int*   ei = (const int*)d_in[1];
    const float* Wq = (const float*)d_in[2];
    const float* bq = (const float*)d_in[3];
    const float* Wk = (const float*)d_in[4];
    const float* bk = (const float*)d_in[5];
    const float* Wv = (const float*)d_in[6];
    const float* bv = (const float*)d_in[7];
    const float* lg = (const float*)d_in[8];
    const float* lb = (const float*)d_in[9];

    const int E = in_sizes[1] / 2;

    float* out  = (float*)d_out;                 // [1, 4096, 256]
    float* attn = out + (size_t)N_NODES * F;     // [1, 4, 4096, 4096]

    zero_adj_kernel<<<(N_NODES * WPR + 255) / 256, 256>>>();
    scatter_edges_kernel<<<(E + 255) / 256, 256>>>(ei, E);

    dim3 gg(N_NODES / BM, 12);
    qkv_gemm_kernel<<<gg, 256>>>(x, Wq, bq, Wk, bk, Wv, bv, attn);

    attn_kernel<<<N_NODES, 128>>>(x, lg, lb, out, attn);
}

// round 4
// speedup vs baseline: 1.2105x; 1.0010x over previous
#include <cuda_runtime.h>
#include <math.h>
#include <stdint.h>

#define N_NODES 4096
#define F 256
#define H 4
#define HD 64
#define WPR (N_NODES / 32)   // 128 bitmap words per row
#define MAXN 256             // max neighbors per row (avg 33; +12 sigma safe)

typedef unsigned long long u64;

// ---- scratch (static device arrays; no allocations allowed) ----
__device__ float g_Q[N_NODES * F];
__device__ float g_K[N_NODES * F];
__device__ float g_V[N_NODES * F];
__device__ unsigned g_adj[N_NODES * WPR];

// ---------------------------------------------------------------------------
// Adjacency bitmap build
// ---------------------------------------------------------------------------
__global__ void zero_adj_kernel() {
    int i = blockIdx.x * blockDim.x + threadIdx.x;
    if (i < N_NODES * WPR) g_adj[i] = 0u;
}

__global__ void scatter_edges_kernel(const int* __restrict__ ei, int E) {
    int i = blockIdx.x * blockDim.x + threadIdx.x;
    if (i >= E) return;
    int s = ei[i];
    int d = ei[E + i];
    atomicOr(&g_adj[s * WPR + (d >> 5)], 1u << (d & 31));
}

// ---------------------------------------------------------------------------
// Fused QKV projection + attn-matrix zeroing.
// BM=128, BN=64, BK=16, 256 threads, 8x4 per thread.
// Inner loop lives entirely in the 64-bit packed-f32x2 domain:
//   - A tile transposed; row-pairs (a,a+1) read as one u64 half of ulonglong2
//   - B tile transposed + duplicated so (b,b) pairs are direct u64 loads
//   - accumulators are u64 with "+l" asm constraint -> no packing MOVs
// Each block also streams a zero slice of the 268MB attn tensor.
// ---------------------------------------------------------------------------
#define BM 128
#define BN 64
#define BK 16
#define NBLK 384                               // 32 x 12 blocks
#define TOT4 16777216u                         // H*N*N/4 float4's to zero
#define SLICE 43692u                           // ceil(TOT4 / NBLK)
#define ZPT 11                                 // zero-stores per thread per k-iter

__global__ __launch_bounds__(256, 2)
void qkv_gemm_kernel(const float* __restrict__ x,
                     const float* __restrict__ Wq, const float* __restrict__ bq,
                     const float* __restrict__ Wk, const float* __restrict__ bk,
                     const float* __restrict__ Wv, const float* __restrict__ bv,
                     float* __restrict__ attn) {
    __shared__ float Ast[BK][BM + 4];        // transposed A tile (row = 528B, 16B-aligned)
    __shared__ float Bst2[BK][2 * BN + 4];   // transposed + duplicated W tile

    const int tid = threadIdx.x;        // 256
    const int tx = tid & 15;            // output col group (4 cols)
    const int ty = tid >> 4;            // output row group (8 rows)
    const int r0 = blockIdx.x * BM;
    const int by = blockIdx.y;          // 0..11
    const int mat = by >> 2;

    const float* W    = (mat == 0) ? Wq : (mat == 1) ? Wk : Wv;
    const float* bias = (mat == 0) ? bq : (mat == 1) ? bk : bv;
    float*       out  = (mat == 0) ? g_Q : (mat == 1) ? g_K : g_V;
    const int o0 = (by & 3) * BN;

    // zero-slice bounds for this block
    const unsigned bid = by * gridDim.x + blockIdx.x;
    const unsigned zs = bid * SLICE;
    const unsigned ze = (zs + SLICE < TOT4) ? zs + SLICE : TOT4;
    float4* __restrict__ zp = (float4*)attn;
    const float4 zero4 = make_float4(0.f, 0.f, 0.f, 0.f);

    // packed accumulators: (0.f,0.f) == 0ull
    u64 acc[4][4] = {};

    int iter = 0;
    for (int k0 = 0; k0 < F; k0 += BK, iter++) {
        // A tile (128x16) transposed: 2 float4 per thread
#pragma unroll
        for (int it = 0; it < 2; it++) {
            int lin = tid + it * 256;
            int r = lin >> 2;
            int kc = lin & 3;
            float4 v = *(const float4*)&x[(r0 + r) * F + k0 + kc * 4];
            Ast[kc * 4 + 0][r] = v.x;
            Ast[kc * 4 + 1][r] = v.y;
            Ast[kc * 4 + 2][r] = v.z;
            Ast[kc * 4 + 3][r] = v.w;
        }
        // B tile (64 outs x 16 k) transposed + duplicated: 1 float4 per thread
        {
            int o = tid >> 2;
            int kc = tid & 3;
            float4 v = *(const float4*)&W[(o0 + o) * F + k0 + kc * 4];
            Bst2[kc * 4 + 0][2 * o] = v.x; Bst2[kc * 4 + 0][2 * o + 1] = v.x;
            Bst2[kc * 4 + 1][2 * o] = v.y; Bst2[kc * 4 + 1][2 * o + 1] = v.y;
            Bst2[kc * 4 + 2][2 * o] = v.z; Bst2[kc * 4 + 2][2 * o + 1] = v.z;
            Bst2[kc * 4 + 3][2 * o] = v.w; Bst2[kc * 4 + 3][2 * o + 1] = v.w;
        }

        // interleaved zero-streaming of the attn slice (fire-and-forget)
#pragma unroll
        for (int t = 0; t < ZPT; t++) {
            unsigned idx = zs + (unsigned)(iter * ZPT + t) * 256u + (unsigned)tid;
            if (idx < ze) zp[idx] = zero4;
        }

        __syncthreads();

#pragma unroll
        for (int kk = 0; kk < BK; kk++) {
            // LDS.128 with explicitly pair-aligned 64-bit halves
            ulonglong2 A01 = *(const ulonglong2*)&Ast[kk][ty * 8];       // (a0a1, a2a3)
            ulonglong2 A23 = *(const ulonglong2*)&Ast[kk][ty * 8 + 4];   // (a4a5, a6a7)
            ulonglong2 B01 = *(const ulonglong2*)&Bst2[kk][tx * 8];      // (b0b0, b1b1)
            ulonglong2 B23 = *(const ulonglong2*)&Bst2[kk][tx * 8 + 4];  // (b2b2, b3b3)
            u64 ap[4] = { A01.x, A01.y, A23.x, A23.y };
            u64 bp[4] = { B01.x, B01.y, B23.x, B23.y };
#pragma unroll
            for (int i = 0; i < 4; i++)
#pragma unroll
                for (int j = 0; j < 4; j++)
                    asm("fma.rn.f32x2 %0, %1, %2, %0;"
                        : "+l"(acc[i][j]) : "l"(ap[i]), "l"(bp[j]));
        }
        __syncthreads();
    }

#pragma unroll
    for (int i = 0; i < 4; i++) {
        int r = r0 + ty * 8 + i * 2;
#pragma unroll
        for (int j = 0; j < 4; j++) {
            int o = o0 + tx * 4 + j;
            float bo = bias[o];
            float2 v = *(const float2*)&acc[i][j];
            out[(r + 0) * F + o] = v.x + bo;
            out[(r + 1) * F + o] = v.y + bo;
        }
    }
}

// ---------------------------------------------------------------------------
// Fused sparse attention (scatter into pre-zeroed attn) + residual + LayerNorm
// One block (128 threads = 4 warps) per node row. Warp w owns head w.
// ---------------------------------------------------------------------------
__global__ __launch_bounds__(128, 8)
void attn_kernel(const float* __restrict__ x,
                 const float* __restrict__ ln_g, const float* __restrict__ ln_b,
                 float* __restrict__ out, float* __restrict__ attn) {
    const int row  = blockIdx.x;
    const int tid  = threadIdx.x;
    const int w    = tid >> 5;   // head
    const int lane = tid & 31;

    __shared__ int   s_nbr[MAXN];
    __shared__ float s_scores[H][MAXN];
    __shared__ float s_q[F];
    __shared__ float s_y[F];
    __shared__ int   s_warpcnt[4];
    __shared__ int   s_cnt;
    __shared__ float s_red[8];

    // Q row into smem
    s_q[tid]       = g_Q[row * F + tid];
    s_q[tid + 128] = g_Q[row * F + tid + 128];

    // (1) Extract neighbor list from bitmap, deterministic (scan-based, sorted)
    unsigned word = g_adj[row * WPR + tid];
    int c = __popc(word);
    int sc = c;  // warp inclusive scan
#pragma unroll
    for (int d = 1; d < 32; d <<= 1) {
        int v = __shfl_up_sync(0xffffffffu, sc, d);
        if (lane >= d) sc += v;
    }
    if (lane == 31) s_warpcnt[w] = sc;
    __syncthreads();

    int base = 0;
#pragma unroll
    for (int i = 0; i < 4; i++)
        if (i < w) base += s_warpcnt[i];
    int off = base + sc - c;   // exclusive prefix across the block
    unsigned ww = word;
    while (ww) {
        int b = __ffs(ww) - 1;
        ww &= ww - 1;
        if (off < MAXN) s_nbr[off] = (tid << 5) + b;
        off++;
    }
    if (tid == 127) s_cnt = base + sc;
    __syncthreads();

    int cnt = s_cnt;
    if (cnt > MAXN) cnt = MAXN;

    // (2) Scores: warp w computes Q_h . K_h, 4 neighbors in flight (ILP across
    // independent shfl reduction trees)
    const float invsqrt = 0.125f;  // 1/sqrt(64)
    float2 qh;
    qh.x = s_q[w * HD + lane * 2];
    qh.y = s_q[w * HD + lane * 2 + 1];
    const float* __restrict__ Kbase = g_K + w * HD + lane * 2;
    int j = 0;
    for (; j + 4 <= cnt; j += 4) {
        int m0 = s_nbr[j], m1 = s_nbr[j + 1], m2 = s_nbr[j + 2], m3 = s_nbr[j + 3];
        float2 k0 = *(const float2*)(Kbase + m0 * F);
        float2 k1 = *(const float2*)(Kbase + m1 * F);
        float2 k2 = *(const float2*)(Kbase + m2 * F);
        float2 k3 = *(const float2*)(Kbase + m3 * F);
        float p0 = qh.x * k0.x + qh.y * k0.y;
        float p1 = qh.x * k1.x + qh.y * k1.y;
        float p2 = qh.x * k2.x + qh.y * k2.y;
        float p3 = qh.x * k3.x + qh.y * k3.y;
#pragma unroll
        for (int d = 16; d; d >>= 1) {
            p0 += __shfl_xor_sync(0xffffffffu, p0, d);
            p1 += __shfl_xor_sync(0xffffffffu, p1, d);
            p2 += __shfl_xor_sync(0xffffffffu, p2, d);
            p3 += __shfl_xor_sync(0xffffffffu, p3, d);
        }
        if (lane == 0) {
            s_scores[w][j]     = p0 * invsqrt;
            s_scores[w][j + 1] = p1 * invsqrt;
            s_scores[w][j + 2] = p2 * invsqrt;
            s_scores[w][j + 3] = p3 * invsqrt;
        }
    }
    for (; j < cnt; j++) {
        int m = s_nbr[j];
        float2 kv = *(const float2*)(Kbase + m * F);
        float p = qh.x * kv.x + qh.y * kv.y;
#pragma unroll
        for (int d = 16; d; d >>= 1) p += __shfl_xor_sync(0xffffffffu, p, d);
        if (lane == 0) s_scores[w][j] = p * invsqrt;
    }
    __syncwarp();

    // (3) Softmax over neighbors (per warp/head)
    float mx = -INFINITY;
    for (int t = lane; t < cnt; t += 32) mx = fmaxf(mx, s_scores[w][t]);
#pragma unroll
    for (int d = 16; d; d >>= 1) mx = fmaxf(mx, __shfl_xor_sync(0xffffffffu, mx, d));
    float sum = 0.0f;
    for (int t = lane; t < cnt; t += 32) {
        float e = expf(s_scores[w][t] - mx);
        s_scores[w][t] = e;
        sum += e;
    }
#pragma unroll
    for (int d = 16; d; d >>= 1) sum += __shfl_xor_sync(0xffffffffu, sum, d);
    float inv = 1.0f / sum;

    // (4) Normalize + scatter nonzero probabilities over the pre-zeroed attn
    // rows (zeroed by qkv_gemm_kernel; cross-kernel stream order fences it).
    for (int t = lane; t < cnt; t += 32) {
        float p = s_scores[w][t] * inv;
        s_scores[w][t] = p;
        attn[(size_t)w * N_NODES * N_NODES + (size_t)row * N_NODES + s_nbr[t]] = p;
    }
    __syncwarp();

    // (5) out_h = sum_j p_j * V[nbr_j, h] — 4 independent accumulators
    const float* __restrict__ Vbase = g_V + w * HD + lane * 2;
    float2 a0 = make_float2(0.f, 0.f), a1 = make_float2(0.f, 0.f);
    float2 a2 = make_float2(0.f, 0.f), a3 = make_float2(0.f, 0.f);
    j = 0;
    for (; j + 4 <= cnt; j += 4) {
        float p0 = s_scores[w][j],     p1 = s_scores[w][j + 1];
        float p2 = s_scores[w][j + 2], p3 = s_scores[w][j + 3];
        float2 v0 = *(const float2*)(Vbase + s_nbr[j] * F);
        float2 v1 = *(const float2*)(Vbase + s_nbr[j + 1] * F);
        float2 v2 = *(const float2*)(Vbase + s_nbr[j + 2] * F);
        float2 v3 = *(const float2*)(Vbase + s_nbr[j + 3] * F);
        a0.x += p0 * v0.x; a0.y += p0 * v0.y;
        a1.x += p1 * v1.x; a1.y += p1 * v1.y;
        a2.x += p2 * v2.x; a2.y += p2 * v2.y;
        a3.x += p3 * v3.x; a3.y += p3 * v3.y;
    }
    for (; j < cnt; j++) {
        float p = s_scores[w][j];
        float2 v = *(const float2*)(Vbase + s_nbr[j] * F);
        a0.x += p * v.x; a0.y += p * v.y;
    }
    float2 acc;
    acc.x = (a0.x + a1.x) + (a2.x + a3.x);
    acc.y = (a0.y + a1.y) + (a2.y + a3.y);
    s_y[w * HD + lane * 2]     = acc.x;
    s_y[w * HD + lane * 2 + 1] = acc.y;
    __syncthreads();

    // (6) residual + LayerNorm over 256 channels (2 per thread)
    float y0 = s_y[tid * 2]     + x[row * F + tid * 2];
    float y1 = s_y[tid * 2 + 1] + x[row * F + tid * 2 + 1];
    float ps = y0 + y1;
    float pq = y0 * y0 + y1 * y1;
#pragma unroll
    for (int d = 16; d; d >>= 1) {
        ps += __shfl_xor_sync(0xffffffffu, ps, d);
        pq += __shfl_xor_sync(0xffffffffu, pq, d);
    }
    if (lane == 0) { s_red[w] = ps; s_red[4 + w] = pq; }
    __syncthreads();
    float tot  = s_red[0] + s_red[1] + s_red[2] + s_red[3];
    float totq = s_red[4] + s_red[5] + s_red[6] + s_red[7];
    float mu  = tot * (1.0f / 256.0f);
    float var = totq * (1.0f / 256.0f) - mu * mu;
    float rs  = rsqrtf(var + 1e-5f);
    out[row * F + tid * 2]     = (y0 - mu) * rs * ln_g[tid * 2]     + ln_b[tid * 2];
    out[row * F + tid * 2 + 1] = (y1 - mu) * rs * ln_g[tid * 2 + 1] + ln_b[tid * 2 + 1];
}

// ---------------------------------------------------------------------------
extern "C" void kernel_launch(void* const* d_in, const int* in_sizes, int n_in,
                              void* d_out, int out_size) {
    const float* x  = (const float*)d_in[0];
    const int*   ei = (const int*)d_in[1];
    const float* Wq = (const float*)d_in[2];
    const float* bq = (const float*)d_in[3];
    const float* Wk = (const float*)d_in[4];
    const float* bk = (const float*)d_in[5];
    const float* Wv = (const float*)d_in[6];
    const float* bv = (const float*)d_in[7];
    const float* lg = (const float*)d_in[8];
    const float* lb = (const float*)d_in[9];

    const int E = in_sizes[1] / 2;

    float* out  = (float*)d_out;                 // [1, 4096, 256]
    float* attn = out + (size_t)N_NODES * F;     // [1, 4, 4096, 4096]

    zero_adj_kernel<<<(N_NODES * WPR + 255) / 256, 256>>>();
    scatter_edges_kernel<<<(E + 255) / 256, 256>>>(ei, E);

    dim3 gg(N_NODES / BM, 12);
    qkv_gemm_kernel<<<gg, 256>>>(x, Wq, bq, Wk, bk, Wv, bv, attn);

    attn_kernel<<<N_NODES, 128>>>(x, lg, lb, out, attn);
}

// round 5
// speedup vs baseline: 1.4834x; 1.2254x over previous
#include <cuda_runtime.h>
#include <cuda_bf16.h>
#include <math.h>
#include <stdint.h>

#define N_NODES 4096
#define F 256
#define H 4
#define HD 64
#define WPR (N_NODES / 32)
#define MAXN 256

// ---- scratch (static device arrays; no allocations allowed) ----
__device__ float g_Q[N_NODES * F];
__device__ float g_K[N_NODES * F];
__device__ float g_V[N_NODES * F];
__device__ unsigned g_adj[N_NODES * WPR];
__device__ __nv_bfloat16 g_xh[N_NODES * F];   // x hi (bf16)
__device__ __nv_bfloat16 g_xl[N_NODES * F];   // x residual (bf16)
__device__ __nv_bfloat16 g_Wh[3 * F * F];     // [Wq;Wk;Wv] hi, [768][256]
__device__ __nv_bfloat16 g_Wl[3 * F * F];     // residual

// ---------------------------------------------------------------------------
// PTX helpers
// ---------------------------------------------------------------------------
__device__ __forceinline__ void cp16(void* dst, const void* src) {
    unsigned d = (unsigned)__cvta_generic_to_shared(dst);
    asm volatile("cp.async.cg.shared.global [%0], [%1], 16;" :: "r"(d), "l"(src));
}
__device__ __forceinline__ void ldm4(unsigned* r, const void* p) {
    unsigned a = (unsigned)__cvta_generic_to_shared(p);
    asm volatile("ldmatrix.sync.aligned.m8n8.x4.shared.b16 {%0,%1,%2,%3}, [%4];"
                 : "=r"(r[0]), "=r"(r[1]), "=r"(r[2]), "=r"(r[3]) : "r"(a));
}
__device__ __forceinline__ void mma16816(float* c, const unsigned* a, const unsigned* b) {
    asm volatile(
        "mma.sync.aligned.m16n8k16.row.col.f32.bf16.bf16.f32 "
        "{%0,%1,%2,%3}, {%4,%5,%6,%7}, {%8,%9}, {%0,%1,%2,%3};"
        : "+f"(c[0]), "+f"(c[1]), "+f"(c[2]), "+f"(c[3])
        : "r"(a[0]), "r"(a[1]), "r"(a[2]), "r"(a[3]), "r"(b[0]), "r"(b[1]));
}

// ---------------------------------------------------------------------------
// Prep: bf16 hi/lo split of x and [Wq;Wk;Wv]
// ---------------------------------------------------------------------------
#define NX (N_NODES * F)          // 1048576
#define NW (3 * F * F)            // 196608
__global__ void convert_kernel(const float* __restrict__ x,
                               const float* __restrict__ Wq,
                               const float* __restrict__ Wk,
                               const float* __restrict__ Wv) {
    int i = blockIdx.x * 256 + threadIdx.x;
    float v; __nv_bfloat16 *dh, *dl; int di;
    if (i < NX) { v = x[i]; dh = g_xh; dl = g_xl; di = i; }
    else {
        int j = i - NX; if (j >= NW) return;
        int mat = j >> 16; int e = j & 65535;
        v = (mat == 0 ? Wq : mat == 1 ? Wk : Wv)[e];
        dh = g_Wh; dl = g_Wl; di = j;
    }
    __nv_bfloat16 h = __float2bfloat16(v);
    dh[di] = h;
    dl[di] = __float2bfloat16(v - __bfloat162float(h));
}

// ---------------------------------------------------------------------------
// Adjacency bitmap build
// ---------------------------------------------------------------------------
__global__ void zero_adj_kernel() {
    int i = blockIdx.x * blockDim.x + threadIdx.x;
    if (i < N_NODES * WPR) g_adj[i] = 0u;
}
__global__ void scatter_edges_kernel(const int* __restrict__ ei, int E) {
    int i = blockIdx.x * blockDim.x + threadIdx.x;
    if (i >= E) return;
    int s = ei[i];
    int d = ei[E + i];
    atomicOr(&g_adj[s * WPR + (d >> 5)], 1u << (d & 31));
}

// ---------------------------------------------------------------------------
// Tensor-core QKV GEMM (bf16 hi/lo, 3-term compensated) + head-0 attn zeroing.
// out[4096, 768] = x[4096,256] @ Wcat^T, BM=128 BN=128, grid (32,6) = 192
// blocks = single wave. 256 thr = 8 warps, warp tile 32m x 64n.
// 2-stage cp.async pipeline over k16 steps.
// ---------------------------------------------------------------------------
#define TOTZ4 4194304u            // head-0 plane: 4096*4096/4 float4
#define SLICEZ 21846u             // ceil(TOTZ4/192)

__global__ __launch_bounds__(256, 2)
void qkv_mma_kernel(const float* __restrict__ bq, const float* __restrict__ bk,
                    const float* __restrict__ bv, float* __restrict__ attn) {
    __shared__ __nv_bfloat16 sA[2][2][128][16];  // [stage][h/l][row][k]
    __shared__ __nv_bfloat16 sB[2][2][128][16];

    const int tid  = threadIdx.x;
    const int wid  = tid >> 5;
    const int lane = tid & 31;
    const int wm = wid >> 1;          // 0..3 -> m offset 32*wm
    const int wn = wid & 1;           // 0..1 -> n offset 64*wn
    const int r0 = blockIdx.x * 128;
    const int n0 = blockIdx.y * 128;

    // cp.async mapping: thread t handles row t>>1, (t&1) selects hi/lo part
    const int arow = tid >> 1, ahl = tid & 1;
    const __nv_bfloat16* srcA = (ahl ? g_xl : g_xh) + (r0 + arow) * F;
    const __nv_bfloat16* srcB = (ahl ? g_Wl : g_Wh) + (n0 + arow) * F;

    // ldmatrix per-lane source coordinates
    const int rA = (lane & 7) + ((lane >> 3) & 1) * 8;
    const int cA = (lane & 16) ? 8 : 0;
    const int rB = (lane & 7) + ((lane & 16) ? 8 : 0);
    const int cB = (lane & 8) ? 8 : 0;

    // zero slice (head-0 attn plane)
    const unsigned bid = blockIdx.y * gridDim.x + blockIdx.x;
    const unsigned zs = bid * SLICEZ;
    const unsigned ze = (zs + SLICEZ < TOTZ4) ? zs + SLICEZ : TOTZ4;
    float4* __restrict__ zp = (float4*)attn;
    const float4 zero4 = make_float4(0.f, 0.f, 0.f, 0.f);

    float acc[2][8][4] = {};

    // prologue: stage 0
    cp16(&sA[0][ahl][arow][0], srcA);
    cp16(&sA[0][ahl][arow][8], srcA + 8);
    cp16(&sB[0][ahl][arow][0], srcB);
    cp16(&sB[0][ahl][arow][8], srcB + 8);
    asm volatile("cp.async.commit_group;");

    for (int kt = 0; kt < 16; kt++) {
        const int s = kt & 1;
        if (kt < 15) {
            const __nv_bfloat16* pa = srcA + (kt + 1) * 16;
            const __nv_bfloat16* pb = srcB + (kt + 1) * 16;
            cp16(&sA[s ^ 1][ahl][arow][0], pa);
            cp16(&sA[s ^ 1][ahl][arow][8], pa + 8);
            cp16(&sB[s ^ 1][ahl][arow][0], pb);
            cp16(&sB[s ^ 1][ahl][arow][8], pb + 8);
            asm volatile("cp.async.commit_group;");
            asm volatile("cp.async.wait_group 1;");
        } else {
            asm volatile("cp.async.wait_group 0;");
        }
        __syncthreads();

        // interleaved zero-streaming (fire-and-forget)
#pragma unroll
        for (int z = 0; z < 6; z++) {
            unsigned idx = zs + (unsigned)(kt * 6 + z) * 256u + (unsigned)tid;
            if (idx < ze) zp[idx] = zero4;
        }

        // A fragments (2 m-tiles, hi+lo)
        unsigned ah[2][4], al[2][4];
#pragma unroll
        for (int tm = 0; tm < 2; tm++) {
            int mr = wm * 32 + tm * 16 + rA;
            ldm4(ah[tm], &sA[s][0][mr][cA]);
            ldm4(al[tm], &sA[s][1][mr][cA]);
        }
#pragma unroll
        for (int ng = 0; ng < 4; ng++) {
            unsigned bh[4], bl[4];
            int nr = wn * 64 + ng * 16 + rB;
            ldm4(bh, &sB[s][0][nr][cB]);
            ldm4(bl, &sB[s][1][nr][cB]);
#pragma unroll
            for (int tm = 0; tm < 2; tm++) {
                mma16816(acc[tm][ng * 2 + 0], ah[tm], bh + 0);
                mma16816(acc[tm][ng * 2 + 0], al[tm], bh + 0);
                mma16816(acc[tm][ng * 2 + 0], ah[tm], bl + 0);
                mma16816(acc[tm][ng * 2 + 1], ah[tm], bh + 2);
                mma16816(acc[tm][ng * 2 + 1], al[tm], bh + 2);
                mma16816(acc[tm][ng * 2 + 1], ah[tm], bl + 2);
            }
        }
        __syncthreads();   // protect stage s before it is refilled next iter
    }

    // epilogue: bias + store fp32
    const int g  = lane >> 2;
    const int t2 = (lane & 3) * 2;
    const int matId = blockIdx.y >> 1;             // 128-col band -> matrix
    const float* bias = matId == 0 ? bq : matId == 1 ? bk : bv;
    float* dst = matId == 0 ? g_Q : matId == 1 ? g_K : g_V;
    const int ncol0 = (blockIdx.y & 1) * 128 + wn * 64;
#pragma unroll
    for (int tm = 0; tm < 2; tm++) {
        int r = r0 + wm * 32 + tm * 16 + g;
#pragma unroll
        for (int nt = 0; nt < 8; nt++) {
            int c = ncol0 + nt * 8 + t2;
            float b0 = bias[c], b1 = bias[c + 1];
            float2 v0 = make_float2(acc[tm][nt][0] + b0, acc[tm][nt][1] + b1);
            float2 v1 = make_float2(acc[tm][nt][2] + b0, acc[tm][nt][3] + b1);
            *(float2*)&dst[r * F + c]       = v0;
            *(float2*)&dst[(r + 8) * F + c] = v1;
        }
    }
}

// ---------------------------------------------------------------------------
// Fused sparse attention + heads-1..3 zeroing + residual + LayerNorm
// One block (128 threads = 4 warps) per node row. Warp w owns head w.
// Head 0's attn plane is zeroed by qkv_mma_kernel (prior kernel in stream).
// ---------------------------------------------------------------------------
__global__ __launch_bounds__(128, 8)
void attn_kernel(const float* __restrict__ x,
                 const float* __restrict__ ln_g, const float* __restrict__ ln_b,
                 float* __restrict__ out, float* __restrict__ attn) {
    const int row  = blockIdx.x;
    const int tid  = threadIdx.x;
    const int w    = tid >> 5;
    const int lane = tid & 31;

    // zero this row for heads 1..3 (head 0 done by GEMM kernel)
    {
        const float4 z = make_float4(0.f, 0.f, 0.f, 0.f);
#pragma unroll
        for (int i = 0; i < 24; i++) {
            int idx = i * 128 + tid;              // [0, 3072)
            int h = 1 + (idx >> 10);
            int c4 = idx & 1023;
            ((float4*)(attn + ((size_t)h * N_NODES + row) * N_NODES))[c4] = z;
        }
    }

    __shared__ int   s_nbr[MAXN];
    __shared__ float s_scores[H][MAXN];
    __shared__ float s_q[F];
    __shared__ float s_y[F];
    __shared__ int   s_warpcnt[4];
    __shared__ int   s_cnt;
    __shared__ float s_red[8];

    s_q[tid]       = g_Q[row * F + tid];
    s_q[tid + 128] = g_Q[row * F + tid + 128];

    // neighbor extraction from bitmap (deterministic, sorted)
    unsigned word = g_adj[row * WPR + tid];
    int c = __popc(word);
    int sc = c;
#pragma unroll
    for (int d = 1; d < 32; d <<= 1) {
        int v = __shfl_up_sync(0xffffffffu, sc, d);
        if (lane >= d) sc += v;
    }
    if (lane == 31) s_warpcnt[w] = sc;
    __syncthreads();

    int base = 0;
#pragma unroll
    for (int i = 0; i < 4; i++)
        if (i < w) base += s_warpcnt[i];
    int off = base + sc - c;
    unsigned ww = word;
    while (ww) {
        int b = __ffs(ww) - 1;
        ww &= ww - 1;
        if (off < MAXN) s_nbr[off] = (tid << 5) + b;
        off++;
    }
    if (tid == 127) s_cnt = base + sc;
    __syncthreads();

    int cnt = s_cnt;
    if (cnt > MAXN) cnt = MAXN;

    // scores, 4 neighbors in flight
    const float invsqrt = 0.125f;
    float2 qh;
    qh.x = s_q[w * HD + lane * 2];
    qh.y = s_q[w * HD + lane * 2 + 1];
    const float* __restrict__ Kbase = g_K + w * HD + lane * 2;
    int j = 0;
    for (; j + 4 <= cnt; j += 4) {
        int m0 = s_nbr[j], m1 = s_nbr[j + 1], m2 = s_nbr[j + 2], m3 = s_nbr[j + 3];
        float2 k0 = *(const float2*)(Kbase + m0 * F);
        float2 k1 = *(const float2*)(Kbase + m1 * F);
        float2 k2 = *(const float2*)(Kbase + m2 * F);
        float2 k3 = *(const float2*)(Kbase + m3 * F);
        float p0 = qh.x * k0.x + qh.y * k0.y;
        float p1 = qh.x * k1.x + qh.y * k1.y;
        float p2 = qh.x * k2.x + qh.y * k2.y;
        float p3 = qh.x * k3.x + qh.y * k3.y;
#pragma unroll
        for (int d = 16; d; d >>= 1) {
            p0 += __shfl_xor_sync(0xffffffffu, p0, d);
            p1 += __shfl_xor_sync(0xffffffffu, p1, d);
            p2 += __shfl_xor_sync(0xffffffffu, p2, d);
            p3 += __shfl_xor_sync(0xffffffffu, p3, d);
        }
        if (lane == 0) {
            s_scores[w][j]     = p0 * invsqrt;
            s_scores[w][j + 1] = p1 * invsqrt;
            s_scores[w][j + 2] = p2 * invsqrt;
            s_scores[w][j + 3] = p3 * invsqrt;
        }
    }
    for (; j < cnt; j++) {
        int m = s_nbr[j];
        float2 kv = *(const float2*)(Kbase + m * F);
        float p = qh.x * kv.x + qh.y * kv.y;
#pragma unroll
        for (int d = 16; d; d >>= 1) p += __shfl_xor_sync(0xffffffffu, p, d);
        if (lane == 0) s_scores[w][j] = p * invsqrt;
    }
    __syncwarp();

    // softmax
    float mx = -INFINITY;
    for (int t = lane; t < cnt; t += 32) mx = fmaxf(mx, s_scores[w][t]);
#pragma unroll
    for (int d = 16; d; d >>= 1) mx = fmaxf(mx, __shfl_xor_sync(0xffffffffu, mx, d));
    float sum = 0.0f;
    for (int t = lane; t < cnt; t += 32) {
        float e = expf(s_scores[w][t] - mx);
        s_scores[w][t] = e;
        sum += e;
    }
#pragma unroll
    for (int d = 16; d; d >>= 1) sum += __shfl_xor_sync(0xffffffffu, sum, d);
    float inv = 1.0f / sum;

    // scatter probabilities (zeros already landed: own block for h1-3, GEMM for h0)
    for (int t = lane; t < cnt; t += 32) {
        float p = s_scores[w][t] * inv;
        s_scores[w][t] = p;
        attn[(size_t)w * N_NODES * N_NODES + (size_t)row * N_NODES + s_nbr[t]] = p;
    }
    __syncwarp();

    // AV with 4 independent accumulators
    const float* __restrict__ Vbase = g_V + w * HD + lane * 2;
    float2 a0 = make_float2(0.f, 0.f), a1 = make_float2(0.f, 0.f);
    float2 a2 = make_float2(0.f, 0.f), a3 = make_float2(0.f, 0.f);
    j = 0;
    for (; j + 4 <= cnt; j += 4) {
        float p0 = s_scores[w][j],     p1 = s_scores[w][j + 1];
        float p2 = s_scores[w][j + 2], p3 = s_scores[w][j + 3];
        float2 v0 = *(const float2*)(Vbase + s_nbr[j] * F);
        float2 v1 = *(const float2*)(Vbase + s_nbr[j + 1] * F);
        float2 v2 = *(const float2*)(Vbase + s_nbr[j + 2] * F);
        float2 v3 = *(const float2*)(Vbase + s_nbr[j + 3] * F);
        a0.x += p0 * v0.x; a0.y += p0 * v0.y;
        a1.x += p1 * v1.x; a1.y += p1 * v1.y;
        a2.x += p2 * v2.x; a2.y += p2 * v2.y;
        a3.x += p3 * v3.x; a3.y += p3 * v3.y;
    }
    for (; j < cnt; j++) {
        float p = s_scores[w][j];
        float2 v = *(const float2*)(Vbase + s_nbr[j] * F);
        a0.x += p * v.x; a0.y += p * v.y;
    }
    float2 acc;
    acc.x = (a0.x + a1.x) + (a2.x + a3.x);
    acc.y = (a0.y + a1.y) + (a2.y + a3.y);
    s_y[w * HD + lane * 2]     = acc.x;
    s_y[w * HD + lane * 2 + 1] = acc.y;
    __syncthreads();

    // residual + LayerNorm
    float y0 = s_y[tid * 2]     + x[row * F + tid * 2];
    float y1 = s_y[tid * 2 + 1] + x[row * F + tid * 2 + 1];
    float ps = y0 + y1;
    float pq = y0 * y0 + y1 * y1;
#pragma unroll
    for (int d = 16; d; d >>= 1) {
        ps += __shfl_xor_sync(0xffffffffu, ps, d);
        pq += __shfl_xor_sync(0xffffffffu, pq, d);
    }
    if (lane == 0) { s_red[w] = ps; s_red[4 + w] = pq; }
    __syncthreads();
    float tot  = s_red[0] + s_red[1] + s_red[2] + s_red[3];
    float totq = s_red[4] + s_red[5] + s_red[6] + s_red[7];
    float mu  = tot * (1.0f / 256.0f);
    float var = totq * (1.0f / 256.0f) - mu * mu;
    float rs  = rsqrtf(var + 1e-5f);
    out[row * F + tid * 2]     = (y0 - mu) * rs * ln_g[tid * 2]     + ln_b[tid * 2];
    out[row * F + tid * 2 + 1] = (y1 - mu) * rs * ln_g[tid * 2 + 1] + ln_b[tid * 2 + 1];
}

// ---------------------------------------------------------------------------
extern "C" void kernel_launch(void* const* d_in, const int* in_sizes, int n_in,
                              void* d_out, int out_size) {
    const float* x  = (const float*)d_in[0];
    const int*   ei = (const int*)d_in[1];
    const float* Wq = (const float*)d_in[2];
    const float* bq = (const float*)d_in[3];
    const float* Wk = (const float*)d_in[4];
    const float* bk = (const float*)d_in[5];
    const float* Wv = (const float*)d_in[6];
    const float* bv = (const float*)d_in[7];
    const float* lg = (const float*)d_in[8];
    const float* lb = (const float*)d_in[9];

    const int E = in_sizes[1] / 2;

    float* out  = (float*)d_out;                 // [1, 4096, 256]
    float* attn = out + (size_t)N_NODES * F;     // [1, 4, 4096, 4096]

    convert_kernel<<<(NX + NW + 255) / 256, 256>>>(x, Wq, Wk, Wv);
    zero_adj_kernel<<<(N_NODES * WPR + 255) / 256, 256>>>();
    scatter_edges_kernel<<<(E + 255) / 256, 256>>>(ei, E);

    dim3 gg(32, 6);
    qkv_mma_kernel<<<gg, 256>>>(bq, bk, bv, attn);

    attn_kernel<<<N_NODES, 128>>>(x, lg, lb, out, attn);
}

// round 8
// speedup vs baseline: 1.7260x; 1.1635x over previous
#include <cuda_runtime.h>
#include <cuda_bf16.h>
#include <math.h>
#include <stdint.h>

#define N_NODES 4096
#define F 256
#define H 4
#define HD 64
#define WPR (N_NODES / 32)
#define MAXN 256

typedef __nv_bfloat16 bf16;

// ---- scratch (static device arrays; no allocations allowed) ----
__device__ float g_Q[N_NODES * F];
__device__ float g_K[N_NODES * F];
__device__ float g_V[N_NODES * F];
__device__ unsigned g_adj[N_NODES * WPR];
__device__ bf16 g_xh[N_NODES * F];
__device__ bf16 g_xl[N_NODES * F];
__device__ bf16 g_Wh[3 * F * F];
__device__ bf16 g_Wl[3 * F * F];

// ---------------------------------------------------------------------------
// PTX helpers (all proven in the round-5 passing kernel)
// ---------------------------------------------------------------------------
__device__ __forceinline__ void cp16(void* dst, const void* src) {
    unsigned d = (unsigned)__cvta_generic_to_shared(dst);
    asm volatile("cp.async.cg.shared.global [%0], [%1], 16;" :: "r"(d), "l"(src));
}
__device__ __forceinline__ void ldm4(unsigned* r, const void* p) {
    unsigned a = (unsigned)__cvta_generic_to_shared(p);
    asm volatile("ldmatrix.sync.aligned.m8n8.x4.shared.b16 {%0,%1,%2,%3}, [%4];"
                 : "=r"(r[0]), "=r"(r[1]), "=r"(r[2]), "=r"(r[3]) : "r"(a));
}
__device__ __forceinline__ void mma16816(float* c, const unsigned* a, const unsigned* b) {
    asm volatile(
        "mma.sync.aligned.m16n8k16.row.col.f32.bf16.bf16.f32 "
        "{%0,%1,%2,%3}, {%4,%5,%6,%7}, {%8,%9}, {%0,%1,%2,%3};"
        : "+f"(c[0]), "+f"(c[1]), "+f"(c[2]), "+f"(c[3])
        : "r"(a[0]), "r"(a[1]), "r"(a[2]), "r"(a[3]), "r"(b[0]), "r"(b[1]));
}

// ---------------------------------------------------------------------------
// Prep: bf16 hi/lo split of x and [Wq;Wk;Wv] + adjacency bitmap clear (fused)
// ---------------------------------------------------------------------------
#define NX (N_NODES * F)
#define NW (3 * F * F)
#define NADJ (N_NODES * WPR)
__global__ void convert_kernel(const float* __restrict__ x,
                               const float* __restrict__ Wq,
                               const float* __restrict__ Wk,
                               const float* __restrict__ Wv) {
    int i = blockIdx.x * 256 + threadIdx.x;
    float v; bf16 *dh, *dl; int di;
    if (i < NX) { v = x[i]; dh = g_xh; dl = g_xl; di = i; }
    else if (i < NX + NW) {
        int j = i - NX;
        int mat = j >> 16; int e = j & 65535;
        v = (mat == 0 ? Wq : mat == 1 ? Wk : Wv)[e];
        dh = g_Wh; dl = g_Wl; di = j;
    } else {
        int j = i - NX - NW;
        if (j < NADJ) g_adj[j] = 0u;
        return;
    }
    bf16 h = __float2bfloat16(v);
    dh[di] = h;
    dl[di] = __float2bfloat16(v - __bfloat162float(h));
}

__global__ void scatter_edges_kernel(const int* __restrict__ ei, int E) {
    int i = blockIdx.x * blockDim.x + threadIdx.x;
    if (i >= E) return;
    int s = ei[i];
    int d = ei[E + i];
    atomicOr(&g_adj[s * WPR + (d >> 5)], 1u << (d & 31));
}

// ---------------------------------------------------------------------------
// Tensor-core QKV GEMM (bf16 hi/lo, 3-term) + head-0 attn zeroing via STG.
// BM=64 BN=128, grid (64,6)=384 blocks, 256 thr = 8 warps, warp tile 16x64.
// 3-stage cp.async pipeline, one __syncthreads per k-step, 48B-stride smem.
// ---------------------------------------------------------------------------
#define SA_BYTES (3 * 2 * 64 * 24 * 2)    // 18432
#define SB_BYTES (3 * 2 * 128 * 24 * 2)   // 36864
#define SMEM_QKV (SA_BYTES + SB_BYTES)    // 55296
#define TOT0_4 4194304u                   // head-0 plane in float4
#define SLICE0 10923u                     // ceil(TOT0_4 / 384)

__global__ __launch_bounds__(256, 2)
void qkv_mma_kernel(const float* __restrict__ bq, const float* __restrict__ bk,
                    const float* __restrict__ bv, float* __restrict__ attn) {
    extern __shared__ char dyn[];
    bf16 (*sA)[2][64][24]  = (bf16(*)[2][64][24])dyn;
    bf16 (*sB)[2][128][24] = (bf16(*)[2][128][24])(dyn + SA_BYTES);

    const int tid  = threadIdx.x;
    const int wid  = tid >> 5;
    const int lane = tid & 31;
    const int wm = wid & 3;
    const int wn = wid >> 2;
    const int r0 = blockIdx.x * 64;
    const int n0 = blockIdx.y * 128;
    const unsigned bid = blockIdx.y * 64 + blockIdx.x;

    // cp.async mapping: 256 threads -> 64 rows x 2(h/l) x 2(8-col halves)
    const int arow = tid >> 2, ahl = (tid >> 1) & 1, ahf = tid & 1;
    const bf16* srcA  = (ahl ? g_xl : g_xh) + (r0 + arow) * F + ahf * 8;
    const bf16* srcB0 = (ahl ? g_Wl : g_Wh) + (n0 + arow) * F + ahf * 8;
    const bf16* srcB1 = srcB0 + 64 * F;

    // ldmatrix lane coords
    const int rA = (lane & 7) + ((lane >> 3) & 1) * 8;
    const int cA = (lane & 16) ? 8 : 0;
    const int rB = (lane & 7) + ((lane & 16) ? 8 : 0);
    const int cB = (lane & 8) ? 8 : 0;

    // head-0 zero slice for this block (fire-and-forget STG.128)
    const unsigned zs = bid * SLICE0;
    const unsigned ze = (zs + SLICE0 < TOT0_4) ? zs + SLICE0 : TOT0_4;
    float4* __restrict__ zp = (float4*)attn;
    const float4 z4 = make_float4(0.f, 0.f, 0.f, 0.f);

    float acc[8][4] = {};

    // prologue: stages 0,1
#pragma unroll
    for (int p = 0; p < 2; p++) {
        cp16(&sA[p][ahl][arow][ahf * 8], srcA + p * 16);
        cp16(&sB[p][ahl][arow][ahf * 8], srcB0 + p * 16);
        cp16(&sB[p][ahl][64 + arow][ahf * 8], srcB1 + p * 16);
        asm volatile("cp.async.commit_group;");
    }

    for (int kt = 0; kt < 16; kt++) {
        const int s = kt % 3;
        if (kt < 15) asm volatile("cp.async.wait_group 1;");
        else         asm volatile("cp.async.wait_group 0;");
        __syncthreads();

        if (kt + 2 < 16) {
            const int sn = (kt + 2) % 3;
            cp16(&sA[sn][ahl][arow][ahf * 8], srcA + (kt + 2) * 16);
            cp16(&sB[sn][ahl][arow][ahf * 8], srcB0 + (kt + 2) * 16);
            cp16(&sB[sn][ahl][64 + arow][ahf * 8], srcB1 + (kt + 2) * 16);
            asm volatile("cp.async.commit_group;");
        }
        // interleaved head-0 zero-streaming (3 float4 per thread per iter)
#pragma unroll
        for (int t = 0; t < 3; t++) {
            unsigned idx = zs + (unsigned)(kt * 3 + t) * 256u + (unsigned)tid;
            if (idx < ze) zp[idx] = z4;
        }

        unsigned ah[4], al[4];
        ldm4(ah, &sA[s][0][wm * 16 + rA][cA]);
        ldm4(al, &sA[s][1][wm * 16 + rA][cA]);
#pragma unroll
        for (int ng = 0; ng < 4; ng++) {
            unsigned bh[4], bl[4];
            ldm4(bh, &sB[s][0][wn * 64 + ng * 16 + rB][cB]);
            ldm4(bl, &sB[s][1][wn * 64 + ng * 16 + rB][cB]);
            mma16816(acc[ng * 2 + 0], ah, bh + 0);
            mma16816(acc[ng * 2 + 0], al, bh + 0);
            mma16816(acc[ng * 2 + 0], ah, bl + 0);
            mma16816(acc[ng * 2 + 1], ah, bh + 2);
            mma16816(acc[ng * 2 + 1], al, bh + 2);
            mma16816(acc[ng * 2 + 1], ah, bl + 2);
        }
    }

    // epilogue: bias + fp32 store
    const int g  = lane >> 2;
    const int t2 = (lane & 3) * 2;
    const int matId = blockIdx.y >> 1;
    const float* bias = matId == 0 ? bq : matId == 1 ? bk : bv;
    float* dst = matId == 0 ? g_Q : matId == 1 ? g_K : g_V;
    const int ncol0 = (blockIdx.y & 1) * 128 + wn * 64;
    const int r = r0 + wm * 16 + g;
#pragma unroll
    for (int nt = 0; nt < 8; nt++) {
        int c = ncol0 + nt * 8 + t2;
        float b0 = bias[c], b1 = bias[c + 1];
        *(float2*)&dst[r * F + c]       = make_float2(acc[nt][0] + b0, acc[nt][1] + b1);
        *(float2*)&dst[(r + 8) * F + c] = make_float2(acc[nt][2] + b0, acc[nt][3] + b1);
    }
}

// ---------------------------------------------------------------------------
// Fused sparse attention + heads-1..3 zeroing (STG) + residual + LayerNorm
// One block (128 threads = 4 warps) per node row. Warp w owns head w.
// Head 0's attn plane is zeroed by qkv_mma_kernel (prior in stream).
// [Byte-identical logic to the round-5 passing attn_kernel.]
// ---------------------------------------------------------------------------
__global__ __launch_bounds__(128, 8)
void attn_kernel(const float* __restrict__ x,
                 const float* __restrict__ ln_g, const float* __restrict__ ln_b,
                 float* __restrict__ out, float* __restrict__ attn) {
    const int row  = blockIdx.x;
    const int tid  = threadIdx.x;
    const int w    = tid >> 5;
    const int lane = tid & 31;

    // zero this row for heads 1..3 (head 0 done by GEMM kernel)
    {
        const float4 z = make_float4(0.f, 0.f, 0.f, 0.f);
#pragma unroll
        for (int i = 0; i < 24; i++) {
            int idx = i * 128 + tid;              // [0, 3072)
            int h = 1 + (idx >> 10);
            int c4 = idx & 1023;
            ((float4*)(attn + ((size_t)h * N_NODES + row) * N_NODES))[c4] = z;
        }
    }

    __shared__ int   s_nbr[MAXN];
    __shared__ float s_scores[H][MAXN];
    __shared__ float s_q[F];
    __shared__ float s_y[F];
    __shared__ int   s_warpcnt[4];
    __shared__ int   s_cnt;
    __shared__ float s_red[8];

    s_q[tid]       = g_Q[row * F + tid];
    s_q[tid + 128] = g_Q[row * F + tid + 128];

    // neighbor extraction from bitmap (deterministic, sorted)
    unsigned word = g_adj[row * WPR + tid];
    int c = __popc(word);
    int sc = c;
#pragma unroll
    for (int d = 1; d < 32; d <<= 1) {
        int v = __shfl_up_sync(0xffffffffu, sc, d);
        if (lane >= d) sc += v;
    }
    if (lane == 31) s_warpcnt[w] = sc;
    __syncthreads();

    int base = 0;
#pragma unroll
    for (int i = 0; i < 4; i++)
        if (i < w) base += s_warpcnt[i];
    int off = base + sc - c;
    unsigned ww = word;
    while (ww) {
        int b = __ffs(ww) - 1;
        ww &= ww - 1;
        if (off < MAXN) s_nbr[off] = (tid << 5) + b;
        off++;
    }
    if (tid == 127) s_cnt = base + sc;
    __syncthreads();

    int cnt = s_cnt;
    if (cnt > MAXN) cnt = MAXN;

    // scores, 4 neighbors in flight
    const float invsqrt = 0.125f;
    float2 qh;
    qh.x = s_q[w * HD + lane * 2];
    qh.y = s_q[w * HD + lane * 2 + 1];
    const float* __restrict__ Kbase = g_K + w * HD + lane * 2;
    int j = 0;
    for (; j + 4 <= cnt; j += 4) {
        int m0 = s_nbr[j], m1 = s_nbr[j + 1], m2 = s_nbr[j + 2], m3 = s_nbr[j + 3];
        float2 k0 = *(const float2*)(Kbase + m0 * F);
        float2 k1 = *(const float2*)(Kbase + m1 * F);
        float2 k2 = *(const float2*)(Kbase + m2 * F);
        float2 k3 = *(const float2*)(Kbase + m3 * F);
        float p0 = qh.x * k0.x + qh.y * k0.y;
        float p1 = qh.x * k1.x + qh.y * k1.y;
        float p2 = qh.x * k2.x + qh.y * k2.y;
        float p3 = qh.x * k3.x + qh.y * k3.y;
#pragma unroll
        for (int d = 16; d; d >>= 1) {
            p0 += __shfl_xor_sync(0xffffffffu, p0, d);
            p1 += __shfl_xor_sync(0xffffffffu, p1, d);
            p2 += __shfl_xor_sync(0xffffffffu, p2, d);
            p3 += __shfl_xor_sync(0xffffffffu, p3, d);
        }
        if (lane == 0) {
            s_scores[w][j]     = p0 * invsqrt;
            s_scores[w][j + 1] = p1 * invsqrt;
            s_scores[w][j + 2] = p2 * invsqrt;
            s_scores[w][j + 3] = p3 * invsqrt;
        }
    }
    for (; j < cnt; j++) {
        int m = s_nbr[j];
        float2 kv = *(const float2*)(Kbase + m * F);
        float p = qh.x * kv.x + qh.y * kv.y;
#pragma unroll
        for (int d = 16; d; d >>= 1) p += __shfl_xor_sync(0xffffffffu, p, d);
        if (lane == 0) s_scores[w][j] = p * invsqrt;
    }
    __syncwarp();

    // softmax
    float mx = -INFINITY;
    for (int t = lane; t < cnt; t += 32) mx = fmaxf(mx, s_scores[w][t]);
#pragma unroll
    for (int d = 16; d; d >>= 1) mx = fmaxf(mx, __shfl_xor_sync(0xffffffffu, mx, d));
    float sum = 0.0f;
    for (int t = lane; t < cnt; t += 32) {
        float e = expf(s_scores[w][t] - mx);
        s_scores[w][t] = e;
        sum += e;
    }
#pragma unroll
    for (int d = 16; d; d >>= 1) sum += __shfl_xor_sync(0xffffffffu, sum, d);
    float inv = 1.0f / sum;

    // scatter probabilities (zeros already landed: own block for h1-3, GEMM for h0)
    for (int t = lane; t < cnt; t += 32) {
        float p = s_scores[w][t] * inv;
        s_scores[w][t] = p;
        attn[(size_t)w * N_NODES * N_NODES + (size_t)row * N_NODES + s_nbr[t]] = p;
    }
    __syncwarp();

    // AV with 4 independent accumulators
    const float* __restrict__ Vbase = g_V + w * HD + lane * 2;
    float2 a0 = make_float2(0.f, 0.f), a1 = make_float2(0.f, 0.f);
    float2 a2 = make_float2(0.f, 0.f), a3 = make_float2(0.f, 0.f);
    j = 0;
    for (; j + 4 <= cnt; j += 4) {
        float p0 = s_scores[w][j],     p1 = s_scores[w][j + 1];
        float p2 = s_scores[w][j + 2], p3 = s_scores[w][j + 3];
        float2 v0 = *(const float2*)(Vbase + s_nbr[j] * F);
        float2 v1 = *(const float2*)(Vbase + s_nbr[j + 1] * F);
        float2 v2 = *(const float2*)(Vbase + s_nbr[j + 2] * F);
        float2 v3 = *(const float2*)(Vbase + s_nbr[j + 3] * F);
        a0.x += p0 * v0.x; a0.y += p0 * v0.y;
        a1.x += p1 * v1.x; a1.y += p1 * v1.y;
        a2.x += p2 * v2.x; a2.y += p2 * v2.y;
        a3.x += p3 * v3.x; a3.y += p3 * v3.y;
    }
    for (; j < cnt; j++) {
        float p = s_scores[w][j];
        float2 v = *(const float2*)(Vbase + s_nbr[j] * F);
        a0.x += p * v.x; a0.y += p * v.y;
    }
    float2 acc;
    acc.x = (a0.x + a1.x) + (a2.x + a3.x);
    acc.y = (a0.y + a1.y) + (a2.y + a3.y);
    s_y[w * HD + lane * 2]     = acc.x;
    s_y[w * HD + lane * 2 + 1] = acc.y;
    __syncthreads();

    // residual + LayerNorm
    float y0 = s_y[tid * 2]     + x[row * F + tid * 2];
    float y1 = s_y[tid * 2 + 1] + x[row * F + tid * 2 + 1];
    float ps = y0 + y1;
    float pq = y0 * y0 + y1 * y1;
#pragma unroll
    for (int d = 16; d; d >>= 1) {
        ps += __shfl_xor_sync(0xffffffffu, ps, d);
        pq += __shfl_xor_sync(0xffffffffu, pq, d);
    }
    if (lane == 0) { s_red[w] = ps; s_red[4 + w] = pq; }
    __syncthreads();
    float tot  = s_red[0] + s_red[1] + s_red[2] + s_red[3];
    float totq = s_red[4] + s_red[5] + s_red[6] + s_red[7];
    float mu  = tot * (1.0f / 256.0f);
    float var = totq * (1.0f / 256.0f) - mu * mu;
    float rs  = rsqrtf(var + 1e-5f);
    out[row * F + tid * 2]     = (y0 - mu) * rs * ln_g[tid * 2]     + ln_b[tid * 2];
    out[row * F + tid * 2 + 1] = (y1 - mu) * rs * ln_g[tid * 2 + 1] + ln_b[tid * 2 + 1];
}

// ---------------------------------------------------------------------------
extern "C" void kernel_launch(void* const* d_in, const int* in_sizes, int n_in,
                              void* d_out, int out_size) {
    const float* x  = (const float*)d_in[0];
    const int*   ei = (const int*)d_in[1];
    const float* Wq = (const float*)d_in[2];
    const float* bq = (const float*)d_in[3];
    const float* Wk = (const float*)d_in[4];
    const float* bk = (const float*)d_in[5];
    const float* Wv = (const float*)d_in[6];
    const float* bv = (const float*)d_in[7];
    const float* lg = (const float*)d_in[8];
    const float* lb = (const float*)d_in[9];

    const int E = in_sizes[1] / 2;

    float* out  = (float*)d_out;                 // [1, 4096, 256]
    float* attn = out + (size_t)N_NODES * F;     // [1, 4, 4096, 4096]

    convert_kernel<<<(NX + NW + NADJ + 255) / 256, 256>>>(x, Wq, Wk, Wv);
    scatter_edges_kernel<<<(E + 255) / 256, 256>>>(ei, E);

    cudaFuncSetAttribute(qkv_mma_kernel,
                         cudaFuncAttributeMaxDynamicSharedMemorySize, SMEM_QKV);
    dim3 gg(64, 6);
    qkv_mma_kernel<<<gg, 256, SMEM_QKV>>>(bq, bk, bv, attn);

    attn_kernel<<<N_NODES, 128>>>(x, lg, lb, out, attn);
}